// round 8
// baseline (speedup 1.0000x reference)
#include <cuda_runtime.h>

// ---------------------------------------------------------------------------
// ChordProgressionLoss v8 — v7 core, ONE change: __launch_bounds__(1024, 1).
// Diagnosis: v5/v7 at launch_bounds(1024,2) hit the 32-reg/thread hard cap
// (2048 thr/SM x 32 = 64K regs) while live state needs ~40 regs -> ptxas
// spills to local; measured ~460 issued instrs/unit vs ~190 in source.
// 1 block/SM frees up to 64 regs/thread (32 warps/SM still hides DRAM with
// 4x front-batched LDG.128/warp). Core math unchanged (exact, rel_err 0).
// ---------------------------------------------------------------------------

#define NBLK 296
#define THREADS 1024
#define WPB 32

__device__ unsigned long long g_simSlots[32];
__device__ unsigned long long g_penSlots[32];
__device__ unsigned int       g_count = 0;

__device__ __forceinline__ unsigned pcbit(float f) {
    unsigned b1 = __float_as_uint(f + 12582912.0f);          // low bits = iv
    float t = fmaf(f, 0.0833333358f, -0.45833334f);
    unsigned b2 = __float_as_uint(t + 12582912.0f);          // low bits = iv/12
    unsigned x = b1 - 12u * b2;                              // low5 = iv%12
    return 1u << (x & 31u);
}
__device__ __forceinline__ unsigned pcmask(float4 v) {
    return pcbit(v.x) | pcbit(v.y) | pcbit(v.z) | pcbit(v.w);
}

__device__ __forceinline__ void doChunk(
    float4 pv, float4 tv, int r, int T, bool laneOwn,
    const unsigned* __restrict__ sT60, const uint2* __restrict__ sSim,
    unsigned long long& simAcc, unsigned& penAcc)
{
    unsigned pm = pcmask(pv);
    unsigned tm = pcmask(tv);
    int p  = __popc(pm);                      // 1..4
    int q  = __popc(tm);
    int it = __popc(pm & tm);

    bool own = laneOwn && (r < T);
    uint2 ra = sSim[p * 4 + q];
    if (own) simAcc += (unsigned long long)((unsigned)it * ra.x + ra.y);

    unsigned Tp = sT60[p];                    // 4 jaccard bytes for this p
    unsigned iM0 = __popc(pm & 0x091u), iM1 = __popc(pm & 0x221u), iM2 = __popc(pm & 0x884u);
    unsigned im0 = __popc(pm & 0x089u), im1 = __popc(pm & 0x121u), im2 = __popc(pm & 0x484u);
    // P = {tM0, tm0, tM2, tm2};  Q = {tM1, tm1, -, -}
    unsigned selP = iM0 | (im0 << 4) | (iM2 << 8) | (im2 << 12);
    unsigned selQ = iM1 | (im1 << 4);
    unsigned P = __byte_perm(Tp, 0, selP);
    unsigned Q = __byte_perm(Tp, 0, selQ);

    unsigned Q1 = __shfl_down_sync(0xffffffffu, Q, 1);
    unsigned P2 = __shfl_down_sync(0xffffffffu, P, 2);
    unsigned P3 = __shfl_down_sync(0xffffffffu, P, 3);

    // maj bytes {P.b0, Q1.b0, P2.b2, P3.b0}; min {P.b1, Q1.b1, P2.b3, P3.b1}
    unsigned v1 = __byte_perm(P,  Q1, 0x0040);
    unsigned v2 = __byte_perm(P2, P3, 0x0042);
    unsigned majW = __byte_perm(v1, v2, 0x5410);
    unsigned w1 = __byte_perm(P,  Q1, 0x0051);
    unsigned w2 = __byte_perm(P2, P3, 0x0053);
    unsigned minW = __byte_perm(w1, w2, 0x5410);

    unsigned SM = __dp4a(majW, 0x01010101u, 0u);
    unsigned Sm = __dp4a(minW, 0x01010101u, 0u);
    if (own && (r <= T - 4)) penAcc += (SM > Sm) ? SM : Sm;   // 240*(1-min)
}

__global__ __launch_bounds__(THREADS, 1) void chord_fused(
    const float4* __restrict__ pred, const float4* __restrict__ targ,
    float* __restrict__ out, int T, int nUnits)
{
    __shared__ unsigned sT60[5];
    __shared__ uint2    sSim[21];
    __shared__ unsigned long long redS[WPB], redP[WPB];
    __shared__ bool     sLast;

    const int tid = threadIdx.x;
    if (tid < 5) {
        int p = tid; unsigned w = 0;
        for (int i = 0; i < 4; i++) {
            int dnm = p + 3 - i;
            unsigned t = (dnm > 0) ? (unsigned)((60 * i) / dnm) : 0u;
            w |= (t & 0xFFu) << (8 * i);
        }
        sT60[p] = w;
    }
    if (tid < 16) {
        int p = (tid >> 2) + 1, q = (tid & 3) + 1;
        double r = 1.0 / (((double)p + 12e-6) * ((double)q + 12e-6));
        unsigned R30 = (unsigned)__double2ll_rn(r * 1073741824.0);
        unsigned A30 = (unsigned)__double2ll_rn((1e-6 * (p + q) + 1.2e-11) * r * 1073741824.0);
        sSim[p * 4 + q] = make_uint2(R30, A30);
    }
    __syncthreads();

    const int lane = tid & 31;
    const int wid  = tid >> 5;
    const bool laneOwn = (lane < 29);

    unsigned long long simAcc = 0ull;
    unsigned penAcc = 0u;
    const int rMax = (T > 0) ? (T - 1) : 0;

    for (int u = blockIdx.x * WPB + wid; u < nUnits; u += gridDim.x * WPB) {
        const int base = u * 58;
        const int rA = base + lane;
        const int rB = base + 29 + lane;
        const int cA = (rA < rMax) ? rA : rMax;     // clamp: branchless loads
        const int cB = (rB < rMax) ? rB : rMax;
        float4 pA = pred[cA], tA = targ[cA];        // 4x LDG.128 batched
        float4 pB = pred[cB], tB = targ[cB];

        doChunk(pA, tA, rA, T, laneOwn, sT60, sSim, simAcc, penAcc);
        doChunk(pB, tB, rB, T, laneOwn, sT60, sSim, simAcc, penAcc);
    }

    // warp reduction (exact integers -> order-independent)
    unsigned long long penW = (unsigned long long)penAcc;
    #pragma unroll
    for (int o = 16; o; o >>= 1) {
        simAcc += __shfl_xor_sync(0xffffffffu, simAcc, o);
        penW   += __shfl_xor_sync(0xffffffffu, penW,   o);
    }
    if (lane == 0) { redS[wid] = simAcc; redP[wid] = penW; }
    __syncthreads();

    if (wid == 0) {
        unsigned long long s = redS[lane];
        unsigned long long p = redP[lane];
        #pragma unroll
        for (int o = 16; o; o >>= 1) {
            s += __shfl_xor_sync(0xffffffffu, s, o);
            p += __shfl_xor_sync(0xffffffffu, p, o);
        }
        if (lane == 0) {
            int slot = blockIdx.x & 31;
            atomicAdd(&g_simSlots[slot], s);
            atomicAdd(&g_penSlots[slot], p);
            __threadfence();
            sLast = (atomicAdd(&g_count, 1u) == gridDim.x - 1);
        }
    }
    __syncthreads();

    if (sLast && wid == 0) {
        __threadfence();
        unsigned long long s = *(volatile unsigned long long*)&g_simSlots[lane];
        unsigned long long p = *(volatile unsigned long long*)&g_penSlots[lane];
        #pragma unroll
        for (int o = 16; o; o >>= 1) {
            s += __shfl_xor_sync(0xffffffffu, s, o);
            p += __shfl_xor_sync(0xffffffffu, p, o);
        }
        if (lane == 0) {
            double simMean = ((double)s * (1.0 / 1073741824.0)) / (double)T;
            long long nWin = (long long)T - 3;
            double pen = (nWin > 0) ? (0.5 - (double)p / (480.0 * (double)nWin)) : 0.0;
            out[0] = (float)((1.0 - simMean) + pen);
        }
        g_simSlots[lane] = 0ull;   // self-reset for graph replay
        g_penSlots[lane] = 0ull;
        if (lane == 0) g_count = 0;
    }
}

extern "C" void kernel_launch(void* const* d_in, const int* in_sizes, int n_in,
                              void* d_out, int out_size)
{
    const float4* pred = (const float4*)d_in[0];
    const float4* targ = (const float4*)d_in[1];
    int T1 = in_sizes[0] / 4;
    int T2 = in_sizes[1] / 4;
    int T = (T1 < T2) ? T1 : T2;

    int nUnits = (T + 57) / 58;
    if (nUnits < 1) nUnits = 1;
    int blocks = (nUnits + WPB - 1) / WPB;
    if (blocks > NBLK) blocks = NBLK;

    chord_fused<<<blocks, THREADS>>>(pred, targ, (float*)d_out, T, nUnits);
}

// round 9
// speedup vs baseline: 1.2045x; 1.2045x over previous
#include <cuda_runtime.h>

// ---------------------------------------------------------------------------
// ChordProgressionLoss v9 — occupancy/register sweet spot + f32x2 masks.
// R7 (64 w/SM, spills) = 14.2us; R8 (32 w/SM, no spills) = 17.7us.
// This: 768x2 = 1536 thr/SM -> 42 regs/thread, 48 warps/SM, grid 296.
// Float4s converted to 12-bit masks immediately after load (low liveness);
// magic-add float->int via packed f32x2 (PTX-only; ptxas won't auto-fuse).
// Exact integer/fixed-point accumulators -> deterministic atomics.
// ---------------------------------------------------------------------------

#define NBLK 296
#define THREADS 768
#define WPB 24

__device__ unsigned long long g_simSlots[32];
__device__ unsigned long long g_penSlots[32];
__device__ unsigned int       g_count = 0;

// bits(12582912.0f)=0x4B400000, bits(1/12)=0x3DAAAAAB, bits(-0.45833334f)=0xBEEAAAAB
#define MAGIC2 0x4B4000004B400000ULL
#define INV12_2 0x3DAAAAAB3DAAAAABULL
#define BIAS2  0xBEEAAAABBEEAAAABULL

// pm = OR over 4 values of 1<<(iv%12), via packed f32x2 magic adds.
__device__ __forceinline__ unsigned pcmask(float4 v) {
    unsigned long long dxy, dzw, b1xy, b1zw, t, b2xy, b2zw;
    asm("mov.b64 %0, {%1,%2};" : "=l"(dxy) : "f"(v.x), "f"(v.y));
    asm("mov.b64 %0, {%1,%2};" : "=l"(dzw) : "f"(v.z), "f"(v.w));
    asm("add.rn.f32x2 %0, %1, %2;" : "=l"(b1xy) : "l"(dxy), "l"(MAGIC2));
    asm("add.rn.f32x2 %0, %1, %2;" : "=l"(b1zw) : "l"(dzw), "l"(MAGIC2));
    asm("fma.rn.f32x2 %0, %1, %2, %3;" : "=l"(t) : "l"(dxy), "l"(INV12_2), "l"(BIAS2));
    asm("add.rn.f32x2 %0, %1, %2;" : "=l"(b2xy) : "l"(t), "l"(MAGIC2));
    asm("fma.rn.f32x2 %0, %1, %2, %3;" : "=l"(t) : "l"(dzw), "l"(INV12_2), "l"(BIAS2));
    asm("add.rn.f32x2 %0, %1, %2;" : "=l"(b2zw) : "l"(t), "l"(MAGIC2));
    unsigned a0, a1, a2, a3, q0, q1, q2, q3;
    asm("mov.b64 {%0,%1}, %2;" : "=r"(a0), "=r"(a1) : "l"(b1xy));
    asm("mov.b64 {%0,%1}, %2;" : "=r"(a2), "=r"(a3) : "l"(b1zw));
    asm("mov.b64 {%0,%1}, %2;" : "=r"(q0), "=r"(q1) : "l"(b2xy));
    asm("mov.b64 {%0,%1}, %2;" : "=r"(q2), "=r"(q3) : "l"(b2zw));
    // low5(a - 12*q) = iv % 12  (0x4B400000 has low 22 bits zero)
    unsigned m = (1u << ((a0 - 12u * q0) & 31u))
               | (1u << ((a1 - 12u * q1) & 31u))
               | (1u << ((a2 - 12u * q2) & 31u))
               | (1u << ((a3 - 12u * q3) & 31u));
    return m;
}

__device__ __forceinline__ void doChunk(
    unsigned pm, unsigned tm, int r, int T, bool laneOwn,
    const unsigned* __restrict__ sT60, const uint2* __restrict__ sSim,
    unsigned long long& simAcc, unsigned& penAcc)
{
    int p  = __popc(pm);                      // 1..4
    int q  = __popc(tm);
    int it = __popc(pm & tm);

    bool own = laneOwn && (r < T);
    uint2 ra = sSim[p * 4 + q];
    if (own) simAcc += (unsigned long long)((unsigned)it * ra.x + ra.y);

    unsigned Tp = sT60[p];                    // 4 jaccard bytes for this p
    unsigned iM0 = __popc(pm & 0x091u), iM1 = __popc(pm & 0x221u), iM2 = __popc(pm & 0x884u);
    unsigned im0 = __popc(pm & 0x089u), im1 = __popc(pm & 0x121u), im2 = __popc(pm & 0x484u);
    // P = {tM0, tm0, tM2, tm2};  Q = {tM1, tm1, -, -}
    unsigned selP = iM0 | (im0 << 4) | (iM2 << 8) | (im2 << 12);
    unsigned selQ = iM1 | (im1 << 4);
    unsigned P = __byte_perm(Tp, 0, selP);
    unsigned Q = __byte_perm(Tp, 0, selQ);

    unsigned Q1 = __shfl_down_sync(0xffffffffu, Q, 1);
    unsigned P2 = __shfl_down_sync(0xffffffffu, P, 2);
    unsigned P3 = __shfl_down_sync(0xffffffffu, P, 3);

    // maj bytes {P.b0, Q1.b0, P2.b2, P3.b0}; min {P.b1, Q1.b1, P2.b3, P3.b1}
    unsigned v1 = __byte_perm(P,  Q1, 0x0040);
    unsigned v2 = __byte_perm(P2, P3, 0x0042);
    unsigned majW = __byte_perm(v1, v2, 0x5410);
    unsigned w1 = __byte_perm(P,  Q1, 0x0051);
    unsigned w2 = __byte_perm(P2, P3, 0x0053);
    unsigned minW = __byte_perm(w1, w2, 0x5410);

    unsigned SM = __dp4a(majW, 0x01010101u, 0u);
    unsigned Sm = __dp4a(minW, 0x01010101u, 0u);
    if (own && (r <= T - 4)) penAcc += (SM > Sm) ? SM : Sm;   // 240*(1-min)
}

__global__ __launch_bounds__(THREADS, 2) void chord_fused(
    const float4* __restrict__ pred, const float4* __restrict__ targ,
    float* __restrict__ out, int T, int nUnits)
{
    __shared__ unsigned sT60[5];
    __shared__ uint2    sSim[21];
    __shared__ unsigned long long redS[WPB], redP[WPB];
    __shared__ bool     sLast;

    const int tid = threadIdx.x;
    if (tid < 5) {
        int p = tid; unsigned w = 0;
        for (int i = 0; i < 4; i++) {
            int dnm = p + 3 - i;
            unsigned t = (dnm > 0) ? (unsigned)((60 * i) / dnm) : 0u;
            w |= (t & 0xFFu) << (8 * i);
        }
        sT60[p] = w;
    }
    if (tid < 16) {
        int p = (tid >> 2) + 1, q = (tid & 3) + 1;
        double r = 1.0 / (((double)p + 12e-6) * ((double)q + 12e-6));
        unsigned R30 = (unsigned)__double2ll_rn(r * 1073741824.0);
        unsigned A30 = (unsigned)__double2ll_rn((1e-6 * (p + q) + 1.2e-11) * r * 1073741824.0);
        sSim[p * 4 + q] = make_uint2(R30, A30);
    }
    __syncthreads();

    const int lane = tid & 31;
    const int wid  = tid >> 5;
    const bool laneOwn = (lane < 29);

    unsigned long long simAcc = 0ull;
    unsigned penAcc = 0u;
    const int rMax = (T > 0) ? (T - 1) : 0;

    for (int u = blockIdx.x * WPB + wid; u < nUnits; u += gridDim.x * WPB) {
        const int base = u * 58;
        const int rA = base + lane;
        const int rB = base + 29 + lane;
        const int cA = (rA < rMax) ? rA : rMax;     // clamp: branchless loads
        const int cB = (rB < rMax) ? rB : rMax;
        float4 pA = pred[cA], tA = targ[cA];        // 4x LDG.128 batched
        float4 pB = pred[cB], tB = targ[cB];

        // masks immediately: float4s die here (low register liveness)
        unsigned pmA = pcmask(pA), tmA = pcmask(tA);
        unsigned pmB = pcmask(pB), tmB = pcmask(tB);

        doChunk(pmA, tmA, rA, T, laneOwn, sT60, sSim, simAcc, penAcc);
        doChunk(pmB, tmB, rB, T, laneOwn, sT60, sSim, simAcc, penAcc);
    }

    // warp reduction (exact integers -> order-independent)
    unsigned long long penW = (unsigned long long)penAcc;
    #pragma unroll
    for (int o = 16; o; o >>= 1) {
        simAcc += __shfl_xor_sync(0xffffffffu, simAcc, o);
        penW   += __shfl_xor_sync(0xffffffffu, penW,   o);
    }
    if (lane == 0) { redS[wid] = simAcc; redP[wid] = penW; }
    __syncthreads();

    if (wid == 0) {
        unsigned long long s = (lane < WPB) ? redS[lane] : 0ull;
        unsigned long long p = (lane < WPB) ? redP[lane] : 0ull;
        #pragma unroll
        for (int o = 16; o; o >>= 1) {
            s += __shfl_xor_sync(0xffffffffu, s, o);
            p += __shfl_xor_sync(0xffffffffu, p, o);
        }
        if (lane == 0) {
            int slot = blockIdx.x & 31;
            atomicAdd(&g_simSlots[slot], s);
            atomicAdd(&g_penSlots[slot], p);
            __threadfence();
            sLast = (atomicAdd(&g_count, 1u) == gridDim.x - 1);
        }
    }
    __syncthreads();

    if (sLast && wid == 0) {
        __threadfence();
        unsigned long long s = *(volatile unsigned long long*)&g_simSlots[lane];
        unsigned long long p = *(volatile unsigned long long*)&g_penSlots[lane];
        #pragma unroll
        for (int o = 16; o; o >>= 1) {
            s += __shfl_xor_sync(0xffffffffu, s, o);
            p += __shfl_xor_sync(0xffffffffu, p, o);
        }
        if (lane == 0) {
            double simMean = ((double)s * (1.0 / 1073741824.0)) / (double)T;
            long long nWin = (long long)T - 3;
            double pen = (nWin > 0) ? (0.5 - (double)p / (480.0 * (double)nWin)) : 0.0;
            out[0] = (float)((1.0 - simMean) + pen);
        }
        g_simSlots[lane] = 0ull;   // self-reset for graph replay
        g_penSlots[lane] = 0ull;
        if (lane == 0) g_count = 0;
    }
}

extern "C" void kernel_launch(void* const* d_in, const int* in_sizes, int n_in,
                              void* d_out, int out_size)
{
    const float4* pred = (const float4*)d_in[0];
    const float4* targ = (const float4*)d_in[1];
    int T1 = in_sizes[0] / 4;
    int T2 = in_sizes[1] / 4;
    int T = (T1 < T2) ? T1 : T2;

    int nUnits = (T + 57) / 58;
    if (nUnits < 1) nUnits = 1;
    int blocks = (nUnits + WPB - 1) / WPB;
    if (blocks > NBLK) blocks = NBLK;

    chord_fused<<<blocks, THREADS>>>(pred, targ, (float*)d_out, T, nUnits);
}